// round 12
// baseline (speedup 1.0000x reference)
#include <cuda_runtime.h>
#include <cstdint>
#include <cstddef>

#define B_    128
#define T_    1024
#define HID_  512
#define VOC_  128
#define EMB_  16
#define NGRP  16      // independent batch groups
#define GSZ   8       // CTAs per group
#define RPG   8       // batch rows per group
#define RPS   4       // rows per rowset (2 rowsets per group)
#define JPC   64      // hidden columns per CTA
#define SCANT 256

#define WS_PITCH 65
// dynamic smem: Ws[512*65] + Ps[128*64] + 2 x hsm[512*4]
#define SMEM_SCAN ((HID_*WS_PITCH + VOC_*JPC + 2*HID_*RPS)*4)

// ---- device scratch ----
__device__ float g_P[VOC_*HID_];                    // P[v][j] = emb@W_ih^T + b_ih + b_hh
__device__ float g_h[2][NGRP][2][HID_][RPS];        // [parity][g][rowset][j][r]
__device__ float g_hs[(size_t)B_*T_*HID_];          // archived hidden states (256MB)
__device__ int   g_ctr2[NGRP][2];                   // per-rowset monotonic counters

// ---------------------------------------------------------------------------
// Kernel 0: P[v][j] = emb@W_ih^T + b_ih + b_hh; reset counters
// ---------------------------------------------------------------------------
__global__ void prep_kernel(const float* __restrict__ emb, const float* __restrict__ W_ih,
                            const float* __restrict__ b_ih, const float* __restrict__ b_hh)
{
    int i = blockIdx.x*256 + threadIdx.x;    // 65536 threads
    if (i < NGRP*2) ((int*)g_ctr2)[i] = 0;
    int v = i >> 9;
    int j = i & 511;
    float s = b_ih[j] + b_hh[j];
    #pragma unroll
    for (int e = 0; e < EMB_; e++)
        s = fmaf(emb[v*EMB_ + e], W_ih[j*EMB_ + e], s);
    g_P[i] = s;
}

// ---- release/acquire barrier primitives ----
__device__ __forceinline__ void ctr_release_inc(int* p) {
    asm volatile("red.release.gpu.global.add.u32 [%0], 1;" :: "l"(p) : "memory");
}
__device__ __forceinline__ int ctr_acquire_ld(const int* p) {
    int v;
    asm volatile("ld.acquire.gpu.global.u32 %0, [%1];" : "=r"(v) : "l"(p) : "memory");
    return v;
}

// ---------------------------------------------------------------------------
// Kernel 1: persistent scan, two-rowset software pipeline.
// 16 groups x 8 CTAs x 256 thr. Rowsets S0 (rows 0-3) / S1 (rows 4-7) are
// independent recurrences; their exchange barriers interleave so every wait
// has a half-phase of slack. Staging uses __ldcg (L2-coherent, L1 bypass).
// Compute map (jl, kq): col jl, K-quarter kq, 4 rows / 4 accumulators.
// ---------------------------------------------------------------------------
__global__ void __launch_bounds__(SCANT, 1)
scan_kernel(const int* __restrict__ x, const float* __restrict__ W_hh)
{
    extern __shared__ float sm[];
    float* Ws   = sm;                         // [512][65] W slice, k-major padded
    float* Ps   = Ws + HID_*WS_PITCH;         // [128][64] P slice
    float* hsm0 = Ps + VOC_*JPC;              // [512][4] staged h, rowset 0
    float* hsm1 = hsm0 + HID_*RPS;            // [512][4] staged h, rowset 1
    __shared__ float4 redP[3*JPC];            // partials from kq=1..3
    __shared__ float4 redB[2][JPC];           // hn handoff per rowset (for archive)
    __shared__ int    toks[2][RPG];           // double-buffered tokens

    const int cta = blockIdx.x;
    const int g   = cta >> 3;                 // group id
    const int c   = cta & 7;                  // CTA within group
    const int j0  = c * JPC;
    const int tid = threadIdx.x;
    const int jl  = tid & 63;                 // column
    const int kq  = tid >> 6;                 // K quarter (1 warp... 2 warps each? 64 thr)

    // --- prologue: W slice (pitch-65, conflict-free), P slice, zero hsm ---
    for (int i = tid; i < JPC*HID_; i += SCANT) {
        int jj = i >> 9, k = i & 511;
        Ws[k*WS_PITCH + jj] = W_hh[(j0 + jj)*HID_ + k];
    }
    for (int i = tid; i < VOC_*JPC; i += SCANT) {
        int v = i >> 6, jj = i & 63;
        Ps[i] = g_P[v*HID_ + j0 + jj];
    }
    #pragma unroll
    for (int i = 0; i < 2*HID_*RPS/SCANT; i++)
        hsm0[tid + i*SCANT] = 0.f;            // zeros both hsm buffers (contiguous)
    if (tid < RPG) toks[0][tid] = x[(g*RPG + tid)*T_];
    __syncthreads();

    for (int t = 0; t < T_; t++) {
        const int par_w = t & 1;              // epilogue writes g_h[par_w]
        const int par_r = (t - 1) & 1;        // staging reads g_h[par_r]
        const int tgt   = t * GSZ;

        // ===== W0 window: release S1(t-1), wait S0(t); archive S1(t-1) =====
        if (tid == 0) {
            if (t > 0) {
                ctr_release_inc(&g_ctr2[g][1]);
                while (ctr_acquire_ld(&g_ctr2[g][0]) < tgt) { }
            }
        } else if (t > 0 && tid >= 64 && tid < 128) {
            int jl2 = tid - 64;
            float4 hv = redB[1][jl2];
            const float* hp4 = (const float*)&hv;
            size_t base = ((size_t)(g*RPG + RPS)*T_ + (t - 1))*HID_ + j0 + jl2;
            #pragma unroll
            for (int i = 0; i < 4; i++)
                g_hs[base + (size_t)i*T_*HID_] = hp4[i];
        } else if (t > 0 && tid >= 8 && tid < 8 + RPG) {
            toks[t & 1][tid - 8] = x[(g*RPG + tid - 8)*T_ + t];
        }
        __syncthreads();

        // ===== stage S0 =====
        if (t > 0) {
            const float4* src = (const float4*)&g_h[par_r][g][0][0][0];
            float4* dst = (float4*)hsm0;
            dst[tid]       = __ldcg(src + tid);
            dst[tid + 256] = __ldcg(src + tid + 256);
            __syncthreads();
        }

        // ===== compute S0 =====
        {
            float a0 = 0.f, a1 = 0.f, a2 = 0.f, a3 = 0.f;
            const float*  wp = Ws + (kq*128)*WS_PITCH + jl;
            const float4* hp = (const float4*)hsm0 + kq*128;
            #pragma unroll 8
            for (int k = 0; k < 128; k++) {
                float  w  = wp[0];
                float4 h4 = hp[0];
                a0 = fmaf(w, h4.x, a0);
                a1 = fmaf(w, h4.y, a1);
                a2 = fmaf(w, h4.z, a2);
                a3 = fmaf(w, h4.w, a3);
                wp += WS_PITCH; hp += 1;
            }
            if (kq) redP[(kq - 1)*JPC + jl] = make_float4(a0, a1, a2, a3);
            __syncthreads();
            if (kq == 0) {
                float4 p1 = redP[jl], p2 = redP[JPC + jl], p3 = redP[2*JPC + jl];
                const int* tk = &toks[t & 1][0];
                float4 hn;
                hn.x = tanhf(((a0 + p1.x) + (p2.x + p3.x)) + Ps[tk[0]*JPC + jl]);
                hn.y = tanhf(((a1 + p1.y) + (p2.y + p3.y)) + Ps[tk[1]*JPC + jl]);
                hn.z = tanhf(((a2 + p1.z) + (p2.z + p3.z)) + Ps[tk[2]*JPC + jl]);
                hn.w = tanhf(((a3 + p1.w) + (p2.w + p3.w)) + Ps[tk[3]*JPC + jl]);
                *(float4*)&g_h[par_w][g][0][j0 + jl][0] = hn;
                redB[0][jl] = hn;
            }
            __syncthreads();
        }

        // ===== W1 window: release S0(t), wait S1(t); archive S0(t) =====
        if (tid == 0) {
            ctr_release_inc(&g_ctr2[g][0]);
            if (t > 0) {
                while (ctr_acquire_ld(&g_ctr2[g][1]) < tgt) { }
            }
        } else if (tid >= 64 && tid < 128) {
            int jl2 = tid - 64;
            float4 hv = redB[0][jl2];
            const float* hp4 = (const float*)&hv;
            size_t base = ((size_t)(g*RPG)*T_ + t)*HID_ + j0 + jl2;
            #pragma unroll
            for (int i = 0; i < 4; i++)
                g_hs[base + (size_t)i*T_*HID_] = hp4[i];
        }
        __syncthreads();

        // ===== stage S1 =====
        if (t > 0) {
            const float4* src = (const float4*)&g_h[par_r][g][1][0][0];
            float4* dst = (float4*)hsm1;
            dst[tid]       = __ldcg(src + tid);
            dst[tid + 256] = __ldcg(src + tid + 256);
            __syncthreads();
        }

        // ===== compute S1 =====
        {
            float a0 = 0.f, a1 = 0.f, a2 = 0.f, a3 = 0.f;
            const float*  wp = Ws + (kq*128)*WS_PITCH + jl;
            const float4* hp = (const float4*)hsm1 + kq*128;
            #pragma unroll 8
            for (int k = 0; k < 128; k++) {
                float  w  = wp[0];
                float4 h4 = hp[0];
                a0 = fmaf(w, h4.x, a0);
                a1 = fmaf(w, h4.y, a1);
                a2 = fmaf(w, h4.z, a2);
                a3 = fmaf(w, h4.w, a3);
                wp += WS_PITCH; hp += 1;
            }
            if (kq) redP[(kq - 1)*JPC + jl] = make_float4(a0, a1, a2, a3);
            __syncthreads();
            if (kq == 0) {
                float4 p1 = redP[jl], p2 = redP[JPC + jl], p3 = redP[2*JPC + jl];
                const int* tk = &toks[t & 1][RPS];
                float4 hn;
                hn.x = tanhf(((a0 + p1.x) + (p2.x + p3.x)) + Ps[tk[0]*JPC + jl]);
                hn.y = tanhf(((a1 + p1.y) + (p2.y + p3.y)) + Ps[tk[1]*JPC + jl]);
                hn.z = tanhf(((a2 + p1.z) + (p2.z + p3.z)) + Ps[tk[2]*JPC + jl]);
                hn.w = tanhf(((a3 + p1.w) + (p2.w + p3.w)) + Ps[tk[3]*JPC + jl]);
                *(float4*)&g_h[par_w][g][1][j0 + jl][0] = hn;
                redB[1][jl] = hn;
            }
            __syncthreads();
        }
    }

    // final archive: S1(T-1)
    if (tid >= 64 && tid < 128) {
        int jl2 = tid - 64;
        float4 hv = redB[1][jl2];
        const float* hp4 = (const float*)&hv;
        size_t base = ((size_t)(g*RPG + RPS)*T_ + (T_ - 1))*HID_ + j0 + jl2;
        #pragma unroll
        for (int i = 0; i < 4; i++)
            g_hs[base + (size_t)i*T_*HID_] = hp4[i];
    }
}

// ---------------------------------------------------------------------------
// Kernel 2: logits = hs[131072,512] @ W_fc^T[512,128] + b_fc
// ---------------------------------------------------------------------------
__global__ void __launch_bounds__(256)
logits_kernel(const float* __restrict__ W_fc, const float* __restrict__ b_fc,
              float* __restrict__ out)
{
    __shared__ float As [64*33];
    __shared__ float Wsh[128*33];
    const int mb  = blockIdx.x * 64;
    const int tid = threadIdx.x;
    const int tv  = tid & 15;
    const int tm  = tid >> 4;

    float acc[4][8];
    #pragma unroll
    for (int vi = 0; vi < 8; vi++) {
        float bv = b_fc[tv + 16*vi];
        #pragma unroll
        for (int mi = 0; mi < 4; mi++) acc[mi][vi] = bv;
    }

    for (int k0 = 0; k0 < HID_; k0 += 32) {
        #pragma unroll
        for (int i = 0; i < 8; i++) {            // 64x32 A chunk
            int idx = tid + i*256;
            int m = idx >> 5, k = idx & 31;
            As[m*33 + k] = g_hs[(size_t)(mb + m)*HID_ + k0 + k];
        }
        #pragma unroll
        for (int i = 0; i < 16; i++) {           // 128x32 W chunk
            int idx = tid + i*256;
            int v = idx >> 5, k = idx & 31;
            Wsh[v*33 + k] = W_fc[v*HID_ + k0 + k];
        }
        __syncthreads();
        #pragma unroll 8
        for (int k = 0; k < 32; k++) {
            float a[4], w[8];
            #pragma unroll
            for (int mi = 0; mi < 4; mi++) a[mi] = As[(tm*4 + mi)*33 + k];
            #pragma unroll
            for (int vi = 0; vi < 8; vi++) w[vi] = Wsh[(tv + 16*vi)*33 + k];
            #pragma unroll
            for (int mi = 0; mi < 4; mi++)
                #pragma unroll
                for (int vi = 0; vi < 8; vi++)
                    acc[mi][vi] = fmaf(a[mi], w[vi], acc[mi][vi]);
        }
        __syncthreads();
    }
    #pragma unroll
    for (int mi = 0; mi < 4; mi++) {
        size_t row = (size_t)(mb + tm*4 + mi) * VOC_;
        #pragma unroll
        for (int vi = 0; vi < 8; vi++)
            out[row + tv + 16*vi] = acc[mi][vi];
    }
}

// ---------------------------------------------------------------------------
extern "C" void kernel_launch(void* const* d_in, const int* in_sizes, int n_in,
                              void* d_out, int out_size)
{
    const int*   x    = (const int*)  d_in[0];
    const float* emb  = (const float*)d_in[1];
    const float* W_ih = (const float*)d_in[2];
    const float* W_hh = (const float*)d_in[3];
    const float* b_ih = (const float*)d_in[4];
    const float* b_hh = (const float*)d_in[5];
    const float* W_fc = (const float*)d_in[6];
    const float* b_fc = (const float*)d_in[7];
    float* out = (float*)d_out;

    cudaFuncSetAttribute(scan_kernel, cudaFuncAttributeMaxDynamicSharedMemorySize, SMEM_SCAN);

    prep_kernel  <<<256, 256>>>(emb, W_ih, b_ih, b_hh);
    scan_kernel  <<<NGRP*GSZ, SCANT, SMEM_SCAN>>>(x, W_hh);
    logits_kernel<<<(B_*T_)/64, 256>>>(W_fc, b_fc, out);
}

// round 13
// speedup vs baseline: 1.2590x; 1.2590x over previous
#include <cuda_runtime.h>
#include <cstdint>
#include <cstddef>

#define B_    128
#define T_    1024
#define HID_  512
#define VOC_  128
#define EMB_  16
#define NGRP  16      // independent batch groups
#define GSZ   8       // CTAs per group
#define RPG   8       // batch rows per group
#define JPC   64      // hidden columns per CTA
#define SCANT 256

#define WS_PITCH 65
// dynamic smem: Ws[512*65] + Ps[128*64] + hsm[512*8]
#define SMEM_SCAN ((HID_*WS_PITCH + VOC_*JPC + HID_*RPG)*4)

// ---- device scratch ----
__device__ float g_P[VOC_*HID_];                    // P[v][j] = emb@W_ih^T + b_ih + b_hh
__device__ float g_h[2][NGRP][HID_][RPG];           // double-buffered h, [buf][g][j][r]
__device__ float g_hs[(size_t)B_*T_*HID_];          // archived hidden states (256MB)
__device__ int   g_ctr[NGRP];                       // group barrier counters (monotonic)

// ---------------------------------------------------------------------------
// Kernel 0: P[v][j] = emb@W_ih^T + b_ih + b_hh; reset group counters
// ---------------------------------------------------------------------------
__global__ void prep_kernel(const float* __restrict__ emb, const float* __restrict__ W_ih,
                            const float* __restrict__ b_ih, const float* __restrict__ b_hh)
{
    int i = blockIdx.x*256 + threadIdx.x;    // 65536 threads
    if (i < NGRP) g_ctr[i] = 0;
    int v = i >> 9;
    int j = i & 511;
    float s = b_ih[j] + b_hh[j];
    #pragma unroll
    for (int e = 0; e < EMB_; e++)
        s = fmaf(emb[v*EMB_ + e], W_ih[j*EMB_ + e], s);
    g_P[i] = s;
}

// ---- release/acquire group barrier primitives (no MEMBAR) ----
__device__ __forceinline__ void ctr_release_inc(int* p) {
    asm volatile("red.release.gpu.global.add.u32 [%0], 1;" :: "l"(p) : "memory");
}
__device__ __forceinline__ int ctr_acquire_ld(const int* p) {
    int v;
    asm volatile("ld.acquire.gpu.global.u32 %0, [%1];" : "=r"(v) : "l"(p) : "memory");
    return v;
}

// ---------------------------------------------------------------------------
// Kernel 1: persistent scan. 16 groups x 8 CTAs x 256 thr. NO clusters.
// Compute map (proven R6/R8): (jl, rh, kh) - col jl, row-half rh (4 rows),
// K-half kh (256 k). Sync path: stores -> syncthreads -> tid0 release-atomic
// -> acquire spin. Staging via __ldcg (L1-bypass, L2-coherent: peers' stores
// are published to L2 by the release/acquire pair). g_hs archive + token
// prefetch run on otherwise-idle threads during the spin window.
// ---------------------------------------------------------------------------
__global__ void __launch_bounds__(SCANT, 1)
scan_kernel(const int* __restrict__ x, const float* __restrict__ W_hh)
{
    extern __shared__ float sm[];
    float* Ws  = sm;                          // [512][65] W slice, k-major padded
    float* Ps  = Ws + HID_*WS_PITCH;          // [128][64] P slice
    float* hsm = Ps + VOC_*JPC;               // [512][8]  staged h (k-major, rows inner)
    __shared__ float4 redA[2*JPC];            // [rh][jl] K-half-1 partial sums
    __shared__ float4 redB[2*JPC];            // [rh][jl] hn handoff kh0 -> kh1
    __shared__ int    toks[2][RPG];           // double-buffered tokens

    const int cta = blockIdx.x;
    const int g   = cta >> 3;                 // group id
    const int c   = cta & 7;                  // CTA within group
    const int j0  = c * JPC;
    const int tid = threadIdx.x;
    const int jl  = tid & 63;                 // column
    const int rh  = (tid >> 6) & 1;           // row half: rows rh*4 .. rh*4+3
    const int kh  = tid >> 7;                 // K half (warp-uniform)
    const int rid = rh*JPC + jl;

    // --- prologue: W slice (pitch-65, conflict-free), P slice, zero h0 slice ---
    for (int i = tid; i < JPC*HID_; i += SCANT) {
        int jj = i >> 9, k = i & 511;
        Ws[k*WS_PITCH + jj] = W_hh[(j0 + jj)*HID_ + k];
    }
    for (int i = tid; i < VOC_*JPC; i += SCANT) {
        int v = i >> 6, jj = i & 63;
        Ps[i] = g_P[v*HID_ + j0 + jj];
    }
    if (tid < 128)
        ((float4*)&g_h[0][g][j0][0])[tid] = make_float4(0.f, 0.f, 0.f, 0.f);
    if (tid < RPG) toks[0][tid] = x[(g*RPG + tid)*T_];
    __syncthreads();

    int target = GSZ;
    if (tid == 0) {
        ctr_release_inc(&g_ctr[g]);
        while (ctr_acquire_ld(&g_ctr[g]) < target) { }
    }
    __syncthreads();
    target += GSZ;

    const float4* hgsrc0 = (const float4*)&g_h[0][g][0][0];
    const float4* hgsrc1 = (const float4*)&g_h[1][g][0][0];

    for (int t = 0; t < T_; t++) {
        // stage full group h (16KB) from L2 (.cg: L1 bypass, L2 hit)
        const float4* src = (t & 1) ? hgsrc1 : hgsrc0;
        float4* dst4 = (float4*)hsm;
        #pragma unroll
        for (int i = 0; i < 4; i++)
            dst4[tid + i*SCANT] = __ldcg(src + tid + i*SCANT);
        __syncthreads();

        // acc over 4 rows; K-half 0 seeds with the P lookup
        const int* tk = toks[t & 1];
        float a0, a1, a2, a3;
        if (kh == 0) {
            a0 = Ps[tk[rh*4 + 0]*JPC + jl];
            a1 = Ps[tk[rh*4 + 1]*JPC + jl];
            a2 = Ps[tk[rh*4 + 2]*JPC + jl];
            a3 = Ps[tk[rh*4 + 3]*JPC + jl];
        } else {
            a0 = a1 = a2 = a3 = 0.f;
        }

        const float*  wp = Ws + (kh*256)*WS_PITCH + jl;
        const float4* hp = (const float4*)(hsm + kh*256*RPG) + rh;
        #pragma unroll 16
        for (int k = 0; k < 256; k++) {
            float  w  = wp[0];                // 1 wf (32 consecutive lanes)
            float4 h4 = hp[0];                // broadcast LDS.128: 1 wf
            a0 = fmaf(w, h4.x, a0);
            a1 = fmaf(w, h4.y, a1);
            a2 = fmaf(w, h4.z, a2);
            a3 = fmaf(w, h4.w, a3);
            wp += WS_PITCH; hp += 2;
        }

        if (kh) redA[rid] = make_float4(a0, a1, a2, a3);
        __syncthreads();

        if (!kh) {
            float4 p = redA[rid];
            float4 hn;
            hn.x = tanhf(a0 + p.x);
            hn.y = tanhf(a1 + p.y);
            hn.z = tanhf(a2 + p.z);
            hn.w = tanhf(a3 + p.w);
            // publish next-step state (one STG.128) + handoff for archive warps
            *(float4*)&g_h[(t & 1) ^ 1][g][j0 + jl][rh*4] = hn;
            redB[rid] = hn;
        }
        __syncthreads();                      // orders stores before tid0's release

        if (tid == 0) {
            ctr_release_inc(&g_ctr[g]);       // release: publishes whole CTA's stores
            while (ctr_acquire_ld(&g_ctr[g]) < target) { }
        } else if (kh) {
            // archive g_hs during the spin window (ordered by kernel boundary)
            float4 hv = redB[rid];
            const float* hp4 = (const float*)&hv;
            size_t base = ((size_t)(g*RPG + rh*4)*T_ + t)*HID_ + j0 + jl;
            #pragma unroll
            for (int i = 0; i < 4; i++)
                g_hs[base + (size_t)i*T_*HID_] = hp4[i];
        } else if (tid >= 8 && tid < 8 + RPG && t + 1 < T_) {
            toks[(t + 1) & 1][tid - 8] = x[(g*RPG + tid - 8)*T_ + t + 1];
        }
        __syncthreads();                      // acquire by tid0 + sync -> CTA-wide
        target += GSZ;
    }
}

// ---------------------------------------------------------------------------
// Kernel 2: logits = hs[131072,512] @ W_fc^T[512,128] + b_fc
// ---------------------------------------------------------------------------
__global__ void __launch_bounds__(256)
logits_kernel(const float* __restrict__ W_fc, const float* __restrict__ b_fc,
              float* __restrict__ out)
{
    __shared__ float As [64*33];
    __shared__ float Wsh[128*33];
    const int mb  = blockIdx.x * 64;
    const int tid = threadIdx.x;
    const int tv  = tid & 15;
    const int tm  = tid >> 4;

    float acc[4][8];
    #pragma unroll
    for (int vi = 0; vi < 8; vi++) {
        float bv = b_fc[tv + 16*vi];
        #pragma unroll
        for (int mi = 0; mi < 4; mi++) acc[mi][vi] = bv;
    }

    for (int k0 = 0; k0 < HID_; k0 += 32) {
        #pragma unroll
        for (int i = 0; i < 8; i++) {            // 64x32 A chunk
            int idx = tid + i*256;
            int m = idx >> 5, k = idx & 31;
            As[m*33 + k] = g_hs[(size_t)(mb + m)*HID_ + k0 + k];
        }
        #pragma unroll
        for (int i = 0; i < 16; i++) {           // 128x32 W chunk
            int idx = tid + i*256;
            int v = idx >> 5, k = idx & 31;
            Wsh[v*33 + k] = W_fc[v*HID_ + k0 + k];
        }
        __syncthreads();
        #pragma unroll 8
        for (int k = 0; k < 32; k++) {
            float a[4], w[8];
            #pragma unroll
            for (int mi = 0; mi < 4; mi++) a[mi] = As[(tm*4 + mi)*33 + k];
            #pragma unroll
            for (int vi = 0; vi < 8; vi++) w[vi] = Wsh[(tv + 16*vi)*33 + k];
            #pragma unroll
            for (int mi = 0; mi < 4; mi++)
                #pragma unroll
                for (int vi = 0; vi < 8; vi++)
                    acc[mi][vi] = fmaf(a[mi], w[vi], acc[mi][vi]);
        }
        __syncthreads();
    }
    #pragma unroll
    for (int mi = 0; mi < 4; mi++) {
        size_t row = (size_t)(mb + tm*4 + mi) * VOC_;
        #pragma unroll
        for (int vi = 0; vi < 8; vi++)
            out[row + tv + 16*vi] = acc[mi][vi];
    }
}

// ---------------------------------------------------------------------------
extern "C" void kernel_launch(void* const* d_in, const int* in_sizes, int n_in,
                              void* d_out, int out_size)
{
    const int*   x    = (const int*)  d_in[0];
    const float* emb  = (const float*)d_in[1];
    const float* W_ih = (const float*)d_in[2];
    const float* W_hh = (const float*)d_in[3];
    const float* b_ih = (const float*)d_in[4];
    const float* b_hh = (const float*)d_in[5];
    const float* W_fc = (const float*)d_in[6];
    const float* b_fc = (const float*)d_in[7];
    float* out = (float*)d_out;

    cudaFuncSetAttribute(scan_kernel, cudaFuncAttributeMaxDynamicSharedMemorySize, SMEM_SCAN);

    prep_kernel  <<<256, 256>>>(emb, W_ih, b_ih, b_hh);
    scan_kernel  <<<NGRP*GSZ, SCANT, SMEM_SCAN>>>(x, W_hh);
    logits_kernel<<<(B_*T_)/64, 256>>>(W_fc, b_fc, out);
}